// round 14
// baseline (speedup 1.0000x reference)
#include <cuda_runtime.h>
#include <cstdint>
#include <math.h>

// Problem dims
#define BATCH 16
#define SEQ   1024
#define EMB   256
#define NTOK  16384   // BATCH*SEQ
#define NHEAD 8
#define DHEAD 32

// Output layout: logits[16] | probas[16] | final_vector[16*1024*256] | ssm[16*256]
#define OFF_PROBAS 16
#define OFF_FINAL  32
#define OFF_SSM    (32 + NTOK*EMB)

// -------- scratch (device globals; no allocations allowed) --------
__device__ float g_x[NTOK * EMB];
__device__ float g_ln[NTOK * EMB];
__device__ float g_qkv[NTOK * 3 * EMB];
__device__ float g_ctx[NTOK * EMB];
__device__ float g_ffn[NTOK * 4 * EMB];
__device__ float g_xproj[NTOK * EMB];
__device__ float g_hlast[BATCH * EMB];

// ================= PTX helpers =================
__device__ __forceinline__ uint32_t smem_u32(const void* p) {
    uint32_t a;
    asm("{ .reg .u64 t; cvta.to.shared.u64 t, %1; cvt.u32.u64 %0, t; }" : "=r"(a) : "l"(p));
    return a;
}
#define CP_ASYNC16(dst, src) \
    asm volatile("cp.async.cg.shared.global [%0], [%1], 16;" :: "r"(dst), "l"(src) : "memory")
#define CP_COMMIT() asm volatile("cp.async.commit_group;" ::: "memory")
#define CP_WAIT1()  asm volatile("cp.async.wait_group 1;" ::: "memory")
#define CP_WAIT0()  asm volatile("cp.async.wait_group 0;" ::: "memory")

__device__ __forceinline__ uint32_t f2tf32(float v) {
    uint32_t t;
    asm("cvt.rna.tf32.f32 %0, %1;" : "=r"(t) : "f"(v));
    return t;
}

__device__ __forceinline__ void mma_tf32(float* d,
                                         uint32_t a0, uint32_t a1, uint32_t a2, uint32_t a3,
                                         uint32_t b0, uint32_t b1) {
    asm volatile(
        "mma.sync.aligned.m16n8k8.row.col.f32.tf32.tf32.f32 "
        "{%0,%1,%2,%3}, {%4,%5,%6,%7}, {%8,%9}, {%0,%1,%2,%3};"
        : "+f"(d[0]), "+f"(d[1]), "+f"(d[2]), "+f"(d[3])
        : "r"(a0), "r"(a1), "r"(a2), "r"(a3), "r"(b0), "r"(b1));
}

#define MBARRIER_INIT(addr, cnt) \
    asm volatile("mbarrier.init.shared.b64 [%0], %1;" :: "r"(addr), "r"(cnt) : "memory")

// Cluster-scope acquire wait (DSMEM producer release-arrives from peer CTA)
#define MBAR_WAIT_CLU(mbar, par) do { \
    uint32_t _m = (mbar), _p = (par), _d; \
    asm volatile("{\n\t.reg .pred p;\n\tmbarrier.try_wait.parity.acquire.cluster.shared::cta.b64 p, [%1], %2;\n\tselp.b32 %0, 1, 0, p;\n\t}" \
        : "=r"(_d) : "r"(_m), "r"(_p) : "memory"); \
    if (!_d) { \
        asm volatile("{\n\t.reg .pred P1;\n\tWL_%=:\n\tmbarrier.try_wait.parity.acquire.cluster.shared::cta.b64 P1, [%0], %1, 0x989680;\n\t@P1 bra.uni WD_%=;\n\tbra.uni WL_%=;\n\tWD_%=:\n\t}" \
            :: "r"(_m), "r"(_p) : "memory"); \
    } \
} while (0)

// ============================================================================
// 1xTF32 mma.sync GEMM v3: C[M,N] = A[M,K] @ W[N,K]^T (+bias +res +pos, act)
// BM=BN=128, BK=32, 256 threads (4x2 warps, 32x64 warp tile).
// 3-STAGE cp.async ring: chunk c+2 issued right after the top-of-loop sync
// (stage (c+2)%3 == (c-1)%3, readers done by that sync) -> prefetch distance
// ~2 chunk-computes >> DRAM latency. One __syncthreads per chunk.
// wait_group 1 normally; wait_group 0 on the last chunk (tail correctness).
// ============================================================================
#define PAD 36
#define STG_FLOATS (128 * PAD)            // per-operand stage: 4608 floats
#define STAGE_FLOATS (2 * STG_FLOATS)     // A+B per stage (9216 floats)
#define STAGE_BYTES (STAGE_FLOATS * 4)    // 36864 B
#define NSTAGE 3
// total dynamic smem: 3 * 36864 = 110592 B

__global__ __launch_bounds__(256, 2)
void gemm_tc(const float* __restrict__ A, const float* __restrict__ W, int ldw,
             const float* __restrict__ bias, const float* __restrict__ res,
             const float* __restrict__ pos, float* __restrict__ C,
             int M, int N, int K, int act)
{
    extern __shared__ float smem[];   // [3 stages][A 128*36 | B 128*36]

    int tid = threadIdx.x;
    int wid = tid >> 5, lane = tid & 31;
    int wm = wid & 3;          // 0..3 -> 32 rows each
    int wn = wid >> 2;         // 0..1 -> 64 cols each
    int m0 = blockIdx.y * 128;
    int n0 = blockIdx.x * 128;

    uint32_t sbase = smem_u32(smem);

    // G->S load mapping: thread t loads row (t>>1), float4 chunks (t&1)*4 .. +3
    int lrow = tid >> 1;               // 0..127
    int lc0  = (tid & 1) * 4;          // starting float4 chunk (0 or 4)
    const float* gA = A + (size_t)(m0 + lrow) * K;
    const float* gB = W + (size_t)(n0 + lrow) * ldw;
    uint32_t dstA = sbase + (uint32_t)(lrow * PAD * 4) + (uint32_t)(lc0 * 16);
    uint32_t dstB = dstA + (uint32_t)(STG_FLOATS * 4);

    float acc[2][8][4];
    #pragma unroll
    for (int i = 0; i < 2; i++)
        #pragma unroll
        for (int j = 0; j < 8; j++)
            #pragma unroll
            for (int r = 0; r < 4; r++) acc[i][j][r] = 0.f;

    int CCH = K >> 5;

    auto issue_chunk = [&](int c, int stg) {
        uint32_t dA = dstA + (uint32_t)(stg * STAGE_BYTES);
        uint32_t dB = dstB + (uint32_t)(stg * STAGE_BYTES);
        const float* pA = gA + (c << 5);
        const float* pB = gB + (c << 5);
        #pragma unroll
        for (int j = 0; j < 4; j++) {
            CP_ASYNC16(dA + j * 16u, pA + (lc0 + j) * 4);
            CP_ASYNC16(dB + j * 16u, pB + (lc0 + j) * 4);
        }
        CP_COMMIT();
    };

    // prologue: chunks 0 and 1 in flight
    issue_chunk(0, 0);
    if (CCH > 1) issue_chunk(1, 1);

    int qr = lane >> 2;        // 0..7 (groupID)
    int qc = lane & 3;         // 0..3 (threadID_in_group)
    int aoff = (wm * 32 + qr) * PAD + qc;
    int boff = (wn * 64 + qr) * PAD + qc;

    int stg = 0;               // stage holding chunk c
    for (int c = 0; c < CCH; c++) {
        if (c + 1 < CCH) { CP_WAIT1(); } else { CP_WAIT0(); }
        __syncthreads();       // stage 'stg' visible; all warps done reading stage (c-1)%3

        if (c + 2 < CCH) {
            int s2 = stg + 2; if (s2 >= NSTAGE) s2 -= NSTAGE;   // == (c-1)%3, safe
            issue_chunk(c + 2, s2);
        }

        const float* As = smem + stg * STAGE_FLOATS;
        const float* Bs = As + STG_FLOATS;

        #pragma unroll
        for (int ks = 0; ks < 4; ks++) {
            int kb = ks * 8;
            uint32_t af[2][4];
            #pragma unroll
            for (int mi = 0; mi < 2; mi++) {
                const float* ap = As + aoff + mi * 16 * PAD + kb;
                af[mi][0] = f2tf32(ap[0]);
                af[mi][1] = f2tf32(ap[8 * PAD]);
                af[mi][2] = f2tf32(ap[4]);
                af[mi][3] = f2tf32(ap[8 * PAD + 4]);
            }
            #pragma unroll
            for (int ni = 0; ni < 8; ni++) {
                const float* bp = Bs + boff + ni * 8 * PAD + kb;
                uint32_t b0 = f2tf32(bp[0]);
                uint32_t b1 = f2tf32(bp[4]);
                mma_tf32(acc[0][ni], af[0][0], af[0][1], af[0][2], af[0][3], b0, b1);
                mma_tf32(acc[1][ni], af[1][0], af[1][1], af[1][2], af[1][3], b0, b1);
            }
        }
        if (++stg == NSTAGE) stg = 0;
    }

    // epilogue
    #pragma unroll
    for (int mi = 0; mi < 2; mi++) {
        #pragma unroll
        for (int half = 0; half < 2; half++) {
            int m = m0 + wm * 32 + mi * 16 + qr + half * 8;
            float* crow = C + (size_t)m * N;
            const float* rrow = res ? res + (size_t)m * N : nullptr;
            const float* prow = pos ? pos + (size_t)(m & (SEQ - 1)) * N : nullptr;
            #pragma unroll
            for (int ni = 0; ni < 8; ni++) {
                int n = n0 + wn * 64 + ni * 8 + 2 * qc;
                float v0 = acc[mi][ni][half * 2 + 0];
                float v1 = acc[mi][ni][half * 2 + 1];
                if (bias) { v0 += bias[n]; v1 += bias[n + 1]; }
                if (rrow) { v0 += rrow[n]; v1 += rrow[n + 1]; }
                if (prow) { v0 += prow[n]; v1 += prow[n + 1]; }
                if (act == 1) {
                    v0 = 0.5f * v0 * (1.0f + erff(v0 * 0.7071067811865475f));
                    v1 = 0.5f * v1 * (1.0f + erff(v1 * 0.7071067811865475f));
                }
                float2 o; o.x = v0; o.y = v1;
                *(float2*)(crow + n) = o;
            }
        }
    }
}

// ============================================================================
// LayerNorm over E=256. One warp per row.
// ============================================================================
__global__ __launch_bounds__(256)
void ln_kernel(const float* __restrict__ x, const float* __restrict__ g,
               const float* __restrict__ bt, float* __restrict__ y)
{
    int w = threadIdx.x >> 5, lane = threadIdx.x & 31;
    int row = blockIdx.x * 8 + w;
    const float* xr = x + (size_t)row * EMB;
    float4 v1 = *(const float4*)(xr + lane * 4);
    float4 v2 = *(const float4*)(xr + 128 + lane * 4);

    float s  = v1.x + v1.y + v1.z + v1.w + v2.x + v2.y + v2.z + v2.w;
    float ss = v1.x*v1.x + v1.y*v1.y + v1.z*v1.z + v1.w*v1.w
             + v2.x*v2.x + v2.y*v2.y + v2.z*v2.z + v2.w*v2.w;
    #pragma unroll
    for (int o = 16; o; o >>= 1) {
        s  += __shfl_xor_sync(0xFFFFFFFFu, s,  o);
        ss += __shfl_xor_sync(0xFFFFFFFFu, ss, o);
    }
    float mu  = s * (1.0f / EMB);
    float var = ss * (1.0f / EMB) - mu * mu;
    float rs  = rsqrtf(var + 1e-5f);

    float* yr = y + (size_t)row * EMB;
    int c = lane * 4;
    float4 o1, o2;
    o1.x = (v1.x - mu) * rs * g[c + 0] + bt[c + 0];
    o1.y = (v1.y - mu) * rs * g[c + 1] + bt[c + 1];
    o1.z = (v1.z - mu) * rs * g[c + 2] + bt[c + 2];
    o1.w = (v1.w - mu) * rs * g[c + 3] + bt[c + 3];
    o2.x = (v2.x - mu) * rs * g[c + 128] + bt[c + 128];
    o2.y = (v2.y - mu) * rs * g[c + 129] + bt[c + 129];
    o2.z = (v2.z - mu) * rs * g[c + 130] + bt[c + 130];
    o2.w = (v2.w - mu) * rs * g[c + 131] + bt[c + 131];
    *(float4*)(yr + c) = o1;
    *(float4*)(yr + 128 + c) = o2;
}

// ============================================================================
// Flash attention on tensor cores (1xTF32 mma.sync), online softmax.
// (unchanged — measured 179us)
// ============================================================================
__global__ __launch_bounds__(256)
void attn_tc(const float* __restrict__ qkv, float* __restrict__ ctx)
{
    __shared__ uint32_t Ks[32][36];        // [key][dim], tf32 bits
    __shared__ uint32_t Vs[32][36];        // [dim][key], tf32 bits (transposed)
    __shared__ uint32_t Pw[8][32][36];     // per-warp P, tf32 bits

    int b = blockIdx.z, h = blockIdx.y;
    int tid = threadIdx.x;
    int wid = tid >> 5, lane = tid & 31;
    int qr = lane >> 2, qc = lane & 3;
    int qbase = blockIdx.x * 256 + wid * 32;

    const float scale = 0.17677669529663687f;   // 1/sqrt(32)
    const float* base = qkv + (size_t)b * SEQ * 768 + h * DHEAD;

    uint32_t aQ[2][4][4];
    #pragma unroll
    for (int m = 0; m < 2; m++) {
        int r0 = qbase + m * 16 + qr;
        const float* q0 = base + (size_t)r0 * 768;
        const float* q1 = base + (size_t)(r0 + 8) * 768;
        #pragma unroll
        for (int kg = 0; kg < 4; kg++) {
            int col = kg * 8 + qc;
            aQ[m][kg][0] = f2tf32(q0[col] * scale);
            aQ[m][kg][1] = f2tf32(q1[col] * scale);
            aQ[m][kg][2] = f2tf32(q0[col + 4] * scale);
            aQ[m][kg][3] = f2tf32(q1[col + 4] * scale);
        }
    }

    float o[2][4][4];
    #pragma unroll
    for (int m = 0; m < 2; m++)
        #pragma unroll
        for (int nd = 0; nd < 4; nd++)
            #pragma unroll
            for (int r = 0; r < 4; r++) o[m][nd][r] = 0.f;
    float mx[2][2] = { { -1e30f, -1e30f }, { -1e30f, -1e30f } };
    float ll[2][2] = { { 0.f, 0.f }, { 0.f, 0.f } };

    int krow = tid >> 3;
    int kc0  = (tid & 7) * 4;

    for (int kt = 0; kt < SEQ; kt += 32) {
        {
            const float* kp = base + (size_t)(kt + krow) * 768 + 256 + kc0;
            float4 ka = *(const float4*)kp;
            Ks[krow][kc0 + 0] = f2tf32(ka.x);
            Ks[krow][kc0 + 1] = f2tf32(ka.y);
            Ks[krow][kc0 + 2] = f2tf32(ka.z);
            Ks[krow][kc0 + 3] = f2tf32(ka.w);
            const float* vp = base + (size_t)(kt + krow) * 768 + 512 + kc0;
            float4 va = *(const float4*)vp;
            Vs[kc0 + 0][krow] = f2tf32(va.x);
            Vs[kc0 + 1][krow] = f2tf32(va.y);
            Vs[kc0 + 2][krow] = f2tf32(va.z);
            Vs[kc0 + 3][krow] = f2tf32(va.w);
        }
        __syncthreads();

        float c[2][4][4];
        #pragma unroll
        for (int m = 0; m < 2; m++)
            #pragma unroll
            for (int nt = 0; nt < 4; nt++)
                #pragma unroll
                for (int r = 0; r < 4; r++) c[m][nt][r] = 0.f;

        #pragma unroll
        for (int nt = 0; nt < 4; nt++) {
            #pragma unroll
            for (int kg = 0; kg < 4; kg++) {
                uint32_t b0 = Ks[nt * 8 + qr][kg * 8 + qc];
                uint32_t b1 = Ks[nt * 8 + qr][kg * 8 + qc + 4];
                mma_tf32(c[0][nt], aQ[0][kg][0], aQ[0][kg][1], aQ[0][kg][2], aQ[0][kg][3], b0, b1);
                mma_tf32(c[1][nt], aQ[1][kg][0], aQ[1][kg][1], aQ[1][kg][2], aQ[1][kg][3], b0, b1);
            }
        }

        #pragma unroll
        for (int m = 0; m < 2; m++) {
            #pragma unroll
            for (int rh = 0; rh < 2; rh++) {
                float rmax = c[m][0][rh * 2];
                #pragma unroll
                for (int nt = 0; nt < 4; nt++) {
                    rmax = fmaxf(rmax, c[m][nt][rh * 2]);
                    rmax = fmaxf(rmax, c[m][nt][rh * 2 + 1]);
                }
                rmax = fmaxf(rmax, __shfl_xor_sync(0xFFFFFFFFu, rmax, 1));
                rmax = fmaxf(rmax, __shfl_xor_sync(0xFFFFFFFFu, rmax, 2));
                float mold = mx[m][rh];
                float mnew = fmaxf(mold, rmax);
                float alpha = __expf(mold - mnew);
                mx[m][rh] = mnew;
                float s = 0.f;
                #pragma unroll
                for (int nt = 0; nt < 4; nt++) {
                    float p0 = __expf(c[m][nt][rh * 2] - mnew);
                    float p1 = __expf(c[m][nt][rh * 2 + 1] - mnew);
                    c[m][nt][rh * 2] = p0;
                    c[m][nt][rh * 2 + 1] = p1;
                    s += p0 + p1;
                }
                s += __shfl_xor_sync(0xFFFFFFFFu, s, 1);
                s += __shfl_xor_sync(0xFFFFFFFFu, s, 2);
                ll[m][rh] = ll[m][rh] * alpha + s;
                #pragma unroll
                for (int nd = 0; nd < 4; nd++) {
                    o[m][nd][rh * 2]     *= alpha;
                    o[m][nd][rh * 2 + 1] *= alpha;
                }
            }
        }

        #pragma unroll
        for (int m = 0; m < 2; m++) {
            #pragma unroll
            for (int nt = 0; nt < 4; nt++) {
                uint2 v0, v1;
                v0.x = f2tf32(c[m][nt][0]); v0.y = f2tf32(c[m][nt][1]);
                v1.x = f2tf32(c[m][nt][2]); v1.y = f2tf32(c[m][nt][3]);
                *(uint2*)&Pw[wid][m * 16 + qr][nt * 8 + 2 * qc]     = v0;
                *(uint2*)&Pw[wid][m * 16 + qr + 8][nt * 8 + 2 * qc] = v1;
            }
        }
        __syncwarp();

        #pragma unroll
        for (int kg = 0; kg < 4; kg++) {
            uint32_t aP[2][4];
            #pragma unroll
            for (int m = 0; m < 2; m++) {
                const uint32_t* pp = &Pw[wid][m * 16 + qr][kg * 8 + qc];
                aP[m][0] = pp[0];
                aP[m][1] = pp[8 * 36];
                aP[m][2] = pp[4];
                aP[m][3] = pp[8 * 36 + 4];
            }
            #pragma unroll
            for (int nd = 0; nd < 4; nd++) {
                uint32_t b0 = Vs[nd * 8 + qr][kg * 8 + qc];
                uint32_t b1 = Vs[nd * 8 + qr][kg * 8 + qc + 4];
                mma_tf32(o[0][nd], aP[0][0], aP[0][1], aP[0][2], aP[0][3], b0, b1);
                mma_tf32(o[1][nd], aP[1][0], aP[1][1], aP[1][2], aP[1][3], b0, b1);
            }
        }
        __syncthreads();
    }

    #pragma unroll
    for (int m = 0; m < 2; m++) {
        #pragma unroll
        for (int rh = 0; rh < 2; rh++) {
            int qrow = qbase + m * 16 + qr + rh * 8;
            float inv = 1.f / ll[m][rh];
            float* dst = ctx + (size_t)(b * SEQ + qrow) * EMB + h * DHEAD;
            #pragma unroll
            for (int nd = 0; nd < 4; nd++) {
                float2 v;
                v.x = o[m][nd][rh * 2] * inv;
                v.y = o[m][nd][rh * 2 + 1] * inv;
                *(float2*)(dst + nd * 8 + 2 * qc) = v;
            }
        }
    }
}

// ============================================================================
// Sequential RNN scan — cluster version, mbarrier ping-pong sync (R13).
// ============================================================================
#define FMA2(d, a, b, c) asm("fma.rn.f32x2 %0, %1, %2, %3;" : "=l"(d) : "l"(a), "l"(b), "l"(c))

__global__ __launch_bounds__(256) __cluster_dims__(2, 1, 1)
void scan_kernel(const float* __restrict__ xproj, const float* __restrict__ i2h_W,
                 const float* __restrict__ h0, float* __restrict__ hlast)
{
    __shared__ __align__(16) float hs[2][EMB];   // double-buffered full h
    __shared__ float part[256];
    __shared__ __align__(8) uint64_t mbars[2];

    uint32_t rank;
    asm("mov.u32 %0, %%cluster_ctarank;" : "=r"(rank));
    int b   = blockIdx.x >> 1;
    int tid = threadIdx.x;
    int lrow = tid & 127;
    int half = tid >> 7;
    int grow = (int)rank * 128 + lrow;

    ulonglong2 w[32];
    {
        const ulonglong2* wp =
            (const ulonglong2*)(i2h_W + (size_t)grow * 512 + 256 + half * 128);
        #pragma unroll
        for (int i = 0; i < 32; i++) w[i] = wp[i];
    }

    hs[0][tid] = h0[b * EMB + tid];
    if (tid == 0) {
        MBARRIER_INIT(smem_u32(&mbars[0]), 128);
        MBARRIER_INIT(smem_u32(&mbars[1]), 128);
    }
    __syncthreads();
    asm volatile("barrier.cluster.arrive.aligned;" ::: "memory");
    asm volatile("barrier.cluster.wait.aligned;" ::: "memory");

    uint32_t mb[2]  = { smem_u32(&mbars[0]), smem_u32(&mbars[1]) };
    uint32_t rmb[2];
    asm("mapa.shared::cluster.u32 %0, %1, %2;" : "=r"(rmb[0]) : "r"(mb[0]), "r"(rank ^ 1u));
    asm("mapa.shared::cluster.u32 %0, %1, %2;" : "=r"(rmb[1]) : "r"(mb[1]), "r"(rank ^ 1u));

    const float* xp = xproj + (size_t)b * SEQ * EMB + grow;
    uint32_t ph[2] = { 0, 0 };
    int p = 0;
    for (int t = 0; t < SEQ; t++) {
        float xv = 0.f;
        if (half == 0) xv = xp[t * EMB];

        const ulonglong2* h2 = (const ulonglong2*)(hs[p] + half * 128);
        unsigned long long a0, a1, a2, a3;
        asm("mov.b64 %0, {%1, %2};" : "=l"(a0) : "f"(0.0f), "f"(0.0f));
        a1 = a0; a2 = a0; a3 = a0;
        #pragma unroll
        for (int i = 0; i < 32; i += 2) {
            ulonglong2 hv  = h2[i];
            ulonglong2 hv2 = h2[i + 1];
            FMA2(a0, w[i].x,     hv.x,  a0);
            FMA2(a1, w[i].y,     hv.y,  a1);
            FMA2(a2, w[i + 1].x, hv2.x, a2);
            FMA2(a3, w[i + 1].y, hv2.y, a3);
        }
        float f0, f1, f2, f3, f4, f5, f6, f7;
        asm("mov.b64 {%0, %1}, %2;" : "=f"(f0), "=f"(f1) : "l"(a0));
        asm("mov.b64 {%0, %1}, %2;" : "=f"(f2), "=f"(f3) : "l"(a1));
        asm("mov.b64 {%0, %1}, %2;" : "=f"(f4), "=f"(f5) : "l"(a2));
        asm("mov.b64 {%0, %1}, %2;" : "=f"(f6), "=f"(f7) : "l"(a3));
        part[tid] = ((f0 + f1) + (f2 + f3)) + ((f4 + f5) + (f6 + f7));
        __syncthreads();

        int pn = p ^ 1;
        int s = t & 1;
        if (half == 0) {
            float v = tanhf(xv + part[lrow] + part[128 + lrow]);
            v = v > 0.f ? v : 0.f;
            hs[pn][grow] = v;
            uint32_t la = smem_u32(&hs[pn][grow]);
            uint32_t ra;
            asm("mapa.shared::cluster.u32 %0, %1, %2;"
                : "=r"(ra) : "r"(la), "r"(rank ^ 1u));
            asm volatile("st.shared::cluster.f32 [%0], %1;"
                         :: "r"(ra), "f"(v) : "memory");
            asm volatile("mbarrier.arrive.release.cluster.shared::cluster.b64 _, [%0];"
                         :: "r"(rmb[1] * s + rmb[0] * (1 - s)) : "memory");
        }
        __syncthreads();
        MBAR_WAIT_CLU(mb[s], ph[s]);
        ph[s] ^= 1;
        p = pn;
    }
    if (half == 0) hlast[b * EMB + grow] = hs[p][grow];
    asm volatile("barrier.cluster.arrive.aligned;" ::: "memory");
    asm volatile("barrier.cluster.wait.aligned;" ::: "memory");
}

// ============================================================================
// Final head
// ============================================================================
__global__ __launch_bounds__(256)
void final_kernel(const float* __restrict__ hlast, const float* __restrict__ h2o_W,
                  const float* __restrict__ h2o_b, const float* __restrict__ cls_W,
                  const float* __restrict__ cls_b, float* __restrict__ out)
{
    __shared__ float hs[EMB];
    __shared__ float red[EMB];
    int b = blockIdx.x, e = threadIdx.x;
    hs[e] = hlast[b * EMB + e];
    __syncthreads();

    float acc = h2o_b[e];
    const float4* wr = (const float4*)(h2o_W + (size_t)e * EMB);
    const float4* h4 = (const float4*)hs;
    #pragma unroll 16
    for (int k = 0; k < 64; k++) {
        float4 w = __ldg(&wr[k]);
        float4 hv = h4[k];
        acc += w.x*hv.x + w.y*hv.y + w.z*hv.z + w.w*hv.w;
    }
    out[OFF_SSM + b * EMB + e] = acc;
    red[e] = acc * cls_W[e];
    __syncthreads();
    #pragma unroll
    for (int o = 128; o; o >>= 1) {
        if (e < o) red[e] += red[e + o];
        __syncthreads();
    }
    if (e == 0) {
        float logit = red[0] + cls_b[0];
        out[b] = logit;
        out[OFF_PROBAS + b] = 1.f / (1.f + expf(-logit));
    }
}

// ============================================================================
__global__ __launch_bounds__(256)
void copy_kernel(const float* __restrict__ src, float* __restrict__ dst, int n4)
{
    int i = blockIdx.x * blockDim.x + threadIdx.x;
    if (i < n4) ((float4*)dst)[i] = ((const float4*)src)[i];
}

// ============================================================================
extern "C" void kernel_launch(void* const* d_in, const int* in_sizes, int n_in,
                              void* d_out, int out_size)
{
    const float* text_emb = (const float*)d_in[0];
    const float* pos     = (const float*)d_in[4];
    const float* text_W  = (const float*)d_in[5];
    const float* text_b  = (const float*)d_in[6];
    const float* ln1_g   = (const float*)d_in[9];
    const float* ln1_b   = (const float*)d_in[10];
    const float* qkv_W   = (const float*)d_in[11];
    const float* qkv_b   = (const float*)d_in[12];
    const float* out_W   = (const float*)d_in[13];
    const float* out_b   = (const float*)d_in[14];
    const float* ln2_g   = (const float*)d_in[15];
    const float* ln2_b   = (const float*)d_in[16];
    const float* ffn_W1  = (const float*)d_in[17];
    const float* ffn_b1  = (const float*)d_in[18];
    const float* ffn_W2  = (const float*)d_in[19];
    const float* ffn_b2  = (const float*)d_in[20];
    const float* cls_W   = (const float*)d_in[21];
    const float* cls_b   = (const float*)d_in[22];
    const float* i2h_W   = (const float*)d_in[23];
    const float* i2h_b   = (const float*)d_in[24];
    const float* h2o_W   = (const float*)d_in[25];
    const float* h2o_b   = (const float*)d_in[26];
    const float* h0      = (const float*)d_in[27];
    float* out = (float*)d_out;

    float *x, *ln, *qkv, *ctx, *ffn, *xproj, *hlast;
    cudaGetSymbolAddress((void**)&x,     g_x);
    cudaGetSymbolAddress((void**)&ln,    g_ln);
    cudaGetSymbolAddress((void**)&qkv,   g_qkv);
    cudaGetSymbolAddress((void**)&ctx,   g_ctx);
    cudaGetSymbolAddress((void**)&ffn,   g_ffn);
    cudaGetSymbolAddress((void**)&xproj, g_xproj);
    cudaGetSymbolAddress((void**)&hlast, g_hlast);

    const int SMEM_GEMM = NSTAGE * STAGE_BYTES;   // 110592 B
    cudaFuncSetAttribute(gemm_tc, cudaFuncAttributeMaxDynamicSharedMemorySize, SMEM_GEMM);

    // 1) lang = text_emb @ text_W^T + text_b + pos_emb
    gemm_tc<<<dim3(2, 128), 256, SMEM_GEMM>>>(text_emb, text_W, 768, text_b, nullptr, pos,
                                              x, NTOK, EMB, 768, 0);

    // 2) two encoder layers (pre-LN)
    for (int l = 0; l < 2; l++) {
        ln_kernel<<<NTOK / 8, 256>>>(x, ln1_g + l * EMB, ln1_b + l * EMB, ln);
        gemm_tc<<<dim3(6, 128), 256, SMEM_GEMM>>>(ln, qkv_W + (size_t)l * 768 * EMB, EMB,
                                                  qkv_b + l * 768, nullptr, nullptr,
                                                  qkv, NTOK, 768, EMB, 0);
        attn_tc<<<dim3(SEQ / 256, NHEAD, BATCH), 256>>>(qkv, ctx);
        gemm_tc<<<dim3(2, 128), 256, SMEM_GEMM>>>(ctx, out_W + (size_t)l * EMB * EMB, EMB,
                                                  out_b + l * EMB, x, nullptr,
                                                  x, NTOK, EMB, EMB, 0);
        ln_kernel<<<NTOK / 8, 256>>>(x, ln2_g + l * EMB, ln2_b + l * EMB, ln);
        gemm_tc<<<dim3(8, 128), 256, SMEM_GEMM>>>(ln, ffn_W1 + (size_t)l * 1024 * EMB, EMB,
                                                  ffn_b1 + l * 1024, nullptr, nullptr,
                                                  ffn, NTOK, 1024, EMB, 1);
        gemm_tc<<<dim3(2, 128), 256, SMEM_GEMM>>>(ffn, ffn_W2 + (size_t)l * EMB * 1024, 1024,
                                                  ffn_b2 + l * EMB, x, nullptr,
                                                  x, NTOK, EMB, 1024, 0);
    }

    // 3) final_vector -> output
    copy_kernel<<<(NTOK * EMB / 4 + 255) / 256, 256>>>(x, out + OFF_FINAL, NTOK * EMB / 4);

    // 4) xproj = x @ i2h_W[:, :256]^T + i2h_b  (row stride 512)
    gemm_tc<<<dim3(2, 128), 256, SMEM_GEMM>>>(x, i2h_W, 512, i2h_b, nullptr, nullptr,
                                              xproj, NTOK, EMB, EMB, 0);

    // 5) sequential scan (cluster of 2 CTAs per batch, weights in registers)
    scan_kernel<<<BATCH * 2, 256>>>(xproj, i2h_W, h0, hlast);

    // 6) head
    final_kernel<<<BATCH, 256>>>(hlast, h2o_W, h2o_b, cls_W, cls_b, out);
}

// round 17
// speedup vs baseline: 1.0802x; 1.0802x over previous
#include <cuda_runtime.h>
#include <cstdint>
#include <math.h>

// Problem dims
#define BATCH 16
#define SEQ   1024
#define EMB   256
#define NTOK  16384   // BATCH*SEQ
#define NHEAD 8
#define DHEAD 32

// Output layout: logits[16] | probas[16] | final_vector[16*1024*256] | ssm[16*256]
#define OFF_PROBAS 16
#define OFF_FINAL  32
#define OFF_SSM    (32 + NTOK*EMB)

// -------- scratch (device globals; no allocations allowed) --------
__device__ float g_x[NTOK * EMB];
__device__ float g_ln[NTOK * EMB];
__device__ float g_qkv[NTOK * 3 * EMB];
__device__ float g_ctx[NTOK * EMB];
__device__ float g_ffn[NTOK * 4 * EMB];
__device__ float g_xproj[NTOK * EMB];
__device__ float g_hlast[BATCH * EMB];

// ================= PTX helpers =================
__device__ __forceinline__ uint32_t smem_u32(const void* p) {
    uint32_t a;
    asm("{ .reg .u64 t; cvta.to.shared.u64 t, %1; cvt.u32.u64 %0, t; }" : "=r"(a) : "l"(p));
    return a;
}
#define CP_ASYNC16(dst, src) \
    asm volatile("cp.async.cg.shared.global [%0], [%1], 16;" :: "r"(dst), "l"(src) : "memory")
#define CP_COMMIT() asm volatile("cp.async.commit_group;" ::: "memory")
#define CP_WAIT1()  asm volatile("cp.async.wait_group 1;" ::: "memory")
#define CP_WAIT0()  asm volatile("cp.async.wait_group 0;" ::: "memory")

__device__ __forceinline__ uint32_t f2tf32(float v) {
    uint32_t t;
    asm("cvt.rna.tf32.f32 %0, %1;" : "=r"(t) : "f"(v));
    return t;
}

__device__ __forceinline__ void mma_tf32(float* d,
                                         uint32_t a0, uint32_t a1, uint32_t a2, uint32_t a3,
                                         uint32_t b0, uint32_t b1) {
    asm volatile(
        "mma.sync.aligned.m16n8k8.row.col.f32.tf32.tf32.f32 "
        "{%0,%1,%2,%3}, {%4,%5,%6,%7}, {%8,%9}, {%0,%1,%2,%3};"
        : "+f"(d[0]), "+f"(d[1]), "+f"(d[2]), "+f"(d[3])
        : "r"(a0), "r"(a1), "r"(a2), "r"(a3), "r"(b0), "r"(b1));
}

// ============================================================================
// 1xTF32 mma.sync GEMM (R12 configuration — best measured): C = A @ W^T
// (+bias +res +pos, act). BM=BN=128, BK=32, 256 threads, 2-stage cp.async.
// C2: optional second output (same values) — fuses the final_vector copy.
// ============================================================================
#define PAD 36
#define STG_FLOATS (128 * PAD)            // per-operand stage: 4608 floats
#define STAGE_BYTES (2 * STG_FLOATS * 4)  // A+B: 36864 bytes

__global__ __launch_bounds__(256, 2)
void gemm_tc(const float* __restrict__ A, const float* __restrict__ W, int ldw,
             const float* __restrict__ bias, const float* __restrict__ res,
             const float* __restrict__ pos, float* __restrict__ C,
             float* __restrict__ C2,
             int M, int N, int K, int act)
{
    extern __shared__ float smem[];   // [2 stages][A 128*36 | B 128*36]

    int tid = threadIdx.x;
    int wid = tid >> 5, lane = tid & 31;
    int wm = wid & 3;          // 0..3 -> 32 rows each
    int wn = wid >> 2;         // 0..1 -> 64 cols each
    int m0 = blockIdx.y * 128;
    int n0 = blockIdx.x * 128;

    uint32_t sbase = smem_u32(smem);

    int lrow = tid >> 1;               // 0..127
    int lc0  = (tid & 1) * 4;          // starting float4 chunk (0 or 4)
    const float* gA = A + (size_t)(m0 + lrow) * K;
    const float* gB = W + (size_t)(n0 + lrow) * ldw;
    uint32_t dstA = sbase + (uint32_t)(lrow * PAD * 4) + (uint32_t)(lc0 * 16);
    uint32_t dstB = dstA + (uint32_t)(STG_FLOATS * 4);

    float acc[2][8][4];
    #pragma unroll
    for (int i = 0; i < 2; i++)
        #pragma unroll
        for (int j = 0; j < 8; j++)
            #pragma unroll
            for (int r = 0; r < 4; r++) acc[i][j][r] = 0.f;

    int CCH = K >> 5;

    // prefetch chunk 0 -> stage 0
    #pragma unroll
    for (int j = 0; j < 4; j++) {
        CP_ASYNC16(dstA + j * 16u, gA + (lc0 + j) * 4);
        CP_ASYNC16(dstB + j * 16u, gB + (lc0 + j) * 4);
    }
    CP_COMMIT();

    int qr = lane >> 2;        // 0..7 (groupID)
    int qc = lane & 3;         // 0..3 (threadID_in_group)
    int aoff = (wm * 32 + qr) * PAD + qc;
    int boff = (wn * 64 + qr) * PAD + qc;

    for (int c = 0; c < CCH; c++) {
        int st = c & 1;
        if (c + 1 < CCH) {
            int s2 = st ^ 1;
            uint32_t dA = dstA + (uint32_t)(s2 * STAGE_BYTES);
            uint32_t dB = dstB + (uint32_t)(s2 * STAGE_BYTES);
            const float* pA = gA + ((c + 1) << 5);
            const float* pB = gB + ((c + 1) << 5);
            #pragma unroll
            for (int j = 0; j < 4; j++) {
                CP_ASYNC16(dA + j * 16u, pA + (lc0 + j) * 4);
                CP_ASYNC16(dB + j * 16u, pB + (lc0 + j) * 4);
            }
            CP_COMMIT();
            CP_WAIT1();
        } else {
            CP_WAIT0();
        }
        __syncthreads();

        const float* As = smem + st * (2 * STG_FLOATS);
        const float* Bs = As + STG_FLOATS;

        #pragma unroll
        for (int ks = 0; ks < 4; ks++) {
            int kb = ks * 8;
            uint32_t af[2][4];
            #pragma unroll
            for (int mi = 0; mi < 2; mi++) {
                const float* ap = As + aoff + mi * 16 * PAD + kb;
                af[mi][0] = f2tf32(ap[0]);
                af[mi][1] = f2tf32(ap[8 * PAD]);
                af[mi][2] = f2tf32(ap[4]);
                af[mi][3] = f2tf32(ap[8 * PAD + 4]);
            }
            #pragma unroll
            for (int ni = 0; ni < 8; ni++) {
                const float* bp = Bs + boff + ni * 8 * PAD + kb;
                uint32_t b0 = f2tf32(bp[0]);
                uint32_t b1 = f2tf32(bp[4]);
                mma_tf32(acc[0][ni], af[0][0], af[0][1], af[0][2], af[0][3], b0, b1);
                mma_tf32(acc[1][ni], af[1][0], af[1][1], af[1][2], af[1][3], b0, b1);
            }
        }
        __syncthreads();
    }

    // epilogue
    #pragma unroll
    for (int mi = 0; mi < 2; mi++) {
        #pragma unroll
        for (int half = 0; half < 2; half++) {
            int m = m0 + wm * 32 + mi * 16 + qr + half * 8;
            float* crow = C + (size_t)m * N;
            float* c2row = C2 ? C2 + (size_t)m * N : nullptr;
            const float* rrow = res ? res + (size_t)m * N : nullptr;
            const float* prow = pos ? pos + (size_t)(m & (SEQ - 1)) * N : nullptr;
            #pragma unroll
            for (int ni = 0; ni < 8; ni++) {
                int n = n0 + wn * 64 + ni * 8 + 2 * qc;
                float v0 = acc[mi][ni][half * 2 + 0];
                float v1 = acc[mi][ni][half * 2 + 1];
                if (bias) { v0 += bias[n]; v1 += bias[n + 1]; }
                if (rrow) { v0 += rrow[n]; v1 += rrow[n + 1]; }
                if (prow) { v0 += prow[n]; v1 += prow[n + 1]; }
                if (act == 1) {
                    v0 = 0.5f * v0 * (1.0f + erff(v0 * 0.7071067811865475f));
                    v1 = 0.5f * v1 * (1.0f + erff(v1 * 0.7071067811865475f));
                }
                float2 o; o.x = v0; o.y = v1;
                *(float2*)(crow + n) = o;
                if (c2row) *(float2*)(c2row + n) = o;
            }
        }
    }
}

// ============================================================================
// LayerNorm over E=256. One warp per row.
// ============================================================================
__global__ __launch_bounds__(256)
void ln_kernel(const float* __restrict__ x, const float* __restrict__ g,
               const float* __restrict__ bt, float* __restrict__ y)
{
    int w = threadIdx.x >> 5, lane = threadIdx.x & 31;
    int row = blockIdx.x * 8 + w;
    const float* xr = x + (size_t)row * EMB;
    float4 v1 = *(const float4*)(xr + lane * 4);
    float4 v2 = *(const float4*)(xr + 128 + lane * 4);

    float s  = v1.x + v1.y + v1.z + v1.w + v2.x + v2.y + v2.z + v2.w;
    float ss = v1.x*v1.x + v1.y*v1.y + v1.z*v1.z + v1.w*v1.w
             + v2.x*v2.x + v2.y*v2.y + v2.z*v2.z + v2.w*v2.w;
    #pragma unroll
    for (int o = 16; o; o >>= 1) {
        s  += __shfl_xor_sync(0xFFFFFFFFu, s,  o);
        ss += __shfl_xor_sync(0xFFFFFFFFu, ss, o);
    }
    float mu  = s * (1.0f / EMB);
    float var = ss * (1.0f / EMB) - mu * mu;
    float rs  = rsqrtf(var + 1e-5f);

    float* yr = y + (size_t)row * EMB;
    int c = lane * 4;
    float4 o1, o2;
    o1.x = (v1.x - mu) * rs * g[c + 0] + bt[c + 0];
    o1.y = (v1.y - mu) * rs * g[c + 1] + bt[c + 1];
    o1.z = (v1.z - mu) * rs * g[c + 2] + bt[c + 2];
    o1.w = (v1.w - mu) * rs * g[c + 3] + bt[c + 3];
    o2.x = (v2.x - mu) * rs * g[c + 128] + bt[c + 128];
    o2.y = (v2.y - mu) * rs * g[c + 129] + bt[c + 129];
    o2.z = (v2.z - mu) * rs * g[c + 130] + bt[c + 130];
    o2.w = (v2.w - mu) * rs * g[c + 131] + bt[c + 131];
    *(float4*)(yr + c) = o1;
    *(float4*)(yr + 128 + c) = o2;
}

// ============================================================================
// Flash attention on tensor cores (1xTF32 mma.sync), online softmax.
// (R12 exact — measured 179us)
// ============================================================================
__global__ __launch_bounds__(256)
void attn_tc(const float* __restrict__ qkv, float* __restrict__ ctx)
{
    __shared__ uint32_t Ks[32][36];        // [key][dim], tf32 bits
    __shared__ uint32_t Vs[32][36];        // [dim][key], tf32 bits (transposed)
    __shared__ uint32_t Pw[8][32][36];     // per-warp P, tf32 bits

    int b = blockIdx.z, h = blockIdx.y;
    int tid = threadIdx.x;
    int wid = tid >> 5, lane = tid & 31;
    int qr = lane >> 2, qc = lane & 3;
    int qbase = blockIdx.x * 256 + wid * 32;

    const float scale = 0.17677669529663687f;   // 1/sqrt(32)
    const float* base = qkv + (size_t)b * SEQ * 768 + h * DHEAD;

    uint32_t aQ[2][4][4];
    #pragma unroll
    for (int m = 0; m < 2; m++) {
        int r0 = qbase + m * 16 + qr;
        const float* q0 = base + (size_t)r0 * 768;
        const float* q1 = base + (size_t)(r0 + 8) * 768;
        #pragma unroll
        for (int kg = 0; kg < 4; kg++) {
            int col = kg * 8 + qc;
            aQ[m][kg][0] = f2tf32(q0[col] * scale);
            aQ[m][kg][1] = f2tf32(q1[col] * scale);
            aQ[m][kg][2] = f2tf32(q0[col + 4] * scale);
            aQ[m][kg][3] = f2tf32(q1[col + 4] * scale);
        }
    }

    float o[2][4][4];
    #pragma unroll
    for (int m = 0; m < 2; m++)
        #pragma unroll
        for (int nd = 0; nd < 4; nd++)
            #pragma unroll
            for (int r = 0; r < 4; r++) o[m][nd][r] = 0.f;
    float mx[2][2] = { { -1e30f, -1e30f }, { -1e30f, -1e30f } };
    float ll[2][2] = { { 0.f, 0.f }, { 0.f, 0.f } };

    int krow = tid >> 3;
    int kc0  = (tid & 7) * 4;

    for (int kt = 0; kt < SEQ; kt += 32) {
        {
            const float* kp = base + (size_t)(kt + krow) * 768 + 256 + kc0;
            float4 ka = *(const float4*)kp;
            Ks[krow][kc0 + 0] = f2tf32(ka.x);
            Ks[krow][kc0 + 1] = f2tf32(ka.y);
            Ks[krow][kc0 + 2] = f2tf32(ka.z);
            Ks[krow][kc0 + 3] = f2tf32(ka.w);
            const float* vp = base + (size_t)(kt + krow) * 768 + 512 + kc0;
            float4 va = *(const float4*)vp;
            Vs[kc0 + 0][krow] = f2tf32(va.x);
            Vs[kc0 + 1][krow] = f2tf32(va.y);
            Vs[kc0 + 2][krow] = f2tf32(va.z);
            Vs[kc0 + 3][krow] = f2tf32(va.w);
        }
        __syncthreads();

        float c[2][4][4];
        #pragma unroll
        for (int m = 0; m < 2; m++)
            #pragma unroll
            for (int nt = 0; nt < 4; nt++)
                #pragma unroll
                for (int r = 0; r < 4; r++) c[m][nt][r] = 0.f;

        #pragma unroll
        for (int nt = 0; nt < 4; nt++) {
            #pragma unroll
            for (int kg = 0; kg < 4; kg++) {
                uint32_t b0 = Ks[nt * 8 + qr][kg * 8 + qc];
                uint32_t b1 = Ks[nt * 8 + qr][kg * 8 + qc + 4];
                mma_tf32(c[0][nt], aQ[0][kg][0], aQ[0][kg][1], aQ[0][kg][2], aQ[0][kg][3], b0, b1);
                mma_tf32(c[1][nt], aQ[1][kg][0], aQ[1][kg][1], aQ[1][kg][2], aQ[1][kg][3], b0, b1);
            }
        }

        #pragma unroll
        for (int m = 0; m < 2; m++) {
            #pragma unroll
            for (int rh = 0; rh < 2; rh++) {
                float rmax = c[m][0][rh * 2];
                #pragma unroll
                for (int nt = 0; nt < 4; nt++) {
                    rmax = fmaxf(rmax, c[m][nt][rh * 2]);
                    rmax = fmaxf(rmax, c[m][nt][rh * 2 + 1]);
                }
                rmax = fmaxf(rmax, __shfl_xor_sync(0xFFFFFFFFu, rmax, 1));
                rmax = fmaxf(rmax, __shfl_xor_sync(0xFFFFFFFFu, rmax, 2));
                float mold = mx[m][rh];
                float mnew = fmaxf(mold, rmax);
                float alpha = __expf(mold - mnew);
                mx[m][rh] = mnew;
                float s = 0.f;
                #pragma unroll
                for (int nt = 0; nt < 4; nt++) {
                    float p0 = __expf(c[m][nt][rh * 2] - mnew);
                    float p1 = __expf(c[m][nt][rh * 2 + 1] - mnew);
                    c[m][nt][rh * 2] = p0;
                    c[m][nt][rh * 2 + 1] = p1;
                    s += p0 + p1;
                }
                s += __shfl_xor_sync(0xFFFFFFFFu, s, 1);
                s += __shfl_xor_sync(0xFFFFFFFFu, s, 2);
                ll[m][rh] = ll[m][rh] * alpha + s;
                #pragma unroll
                for (int nd = 0; nd < 4; nd++) {
                    o[m][nd][rh * 2]     *= alpha;
                    o[m][nd][rh * 2 + 1] *= alpha;
                }
            }
        }

        #pragma unroll
        for (int m = 0; m < 2; m++) {
            #pragma unroll
            for (int nt = 0; nt < 4; nt++) {
                uint2 v0, v1;
                v0.x = f2tf32(c[m][nt][0]); v0.y = f2tf32(c[m][nt][1]);
                v1.x = f2tf32(c[m][nt][2]); v1.y = f2tf32(c[m][nt][3]);
                *(uint2*)&Pw[wid][m * 16 + qr][nt * 8 + 2 * qc]     = v0;
                *(uint2*)&Pw[wid][m * 16 + qr + 8][nt * 8 + 2 * qc] = v1;
            }
        }
        __syncwarp();

        #pragma unroll
        for (int kg = 0; kg < 4; kg++) {
            uint32_t aP[2][4];
            #pragma unroll
            for (int m = 0; m < 2; m++) {
                const uint32_t* pp = &Pw[wid][m * 16 + qr][kg * 8 + qc];
                aP[m][0] = pp[0];
                aP[m][1] = pp[8 * 36];
                aP[m][2] = pp[4];
                aP[m][3] = pp[8 * 36 + 4];
            }
            #pragma unroll
            for (int nd = 0; nd < 4; nd++) {
                uint32_t b0 = Vs[nd * 8 + qr][kg * 8 + qc];
                uint32_t b1 = Vs[nd * 8 + qr][kg * 8 + qc + 4];
                mma_tf32(o[0][nd], aP[0][0], aP[0][1], aP[0][2], aP[0][3], b0, b1);
                mma_tf32(o[1][nd], aP[1][0], aP[1][1], aP[1][2], aP[1][3], b0, b1);
            }
        }
        __syncthreads();
    }

    #pragma unroll
    for (int m = 0; m < 2; m++) {
        #pragma unroll
        for (int rh = 0; rh < 2; rh++) {
            int qrow = qbase + m * 16 + qr + rh * 8;
            float inv = 1.f / ll[m][rh];
            float* dst = ctx + (size_t)(b * SEQ + qrow) * EMB + h * DHEAD;
            #pragma unroll
            for (int nd = 0; nd < 4; nd++) {
                float2 v;
                v.x = o[m][nd][rh * 2] * inv;
                v.y = o[m][nd][rh * 2 + 1] * inv;
                *(float2*)(dst + nd * 8 + 2 * qc) = v;
            }
        }
    }
}

// ============================================================================
// Sequential RNN scan — cluster version (R12 exact: weights in registers,
// barrier.cluster per step).
// ============================================================================
#define FMA2(d, a, b, c) asm("fma.rn.f32x2 %0, %1, %2, %3;" : "=l"(d) : "l"(a), "l"(b), "l"(c))

__global__ __launch_bounds__(256) __cluster_dims__(2, 1, 1)
void scan_kernel(const float* __restrict__ xproj, const float* __restrict__ i2h_W,
                 const float* __restrict__ h0, float* __restrict__ hlast)
{
    __shared__ __align__(16) float hs[2][EMB];   // double-buffered full h
    __shared__ float part[256];

    uint32_t rank;
    asm("mov.u32 %0, %%cluster_ctarank;" : "=r"(rank));
    int b   = blockIdx.x >> 1;
    int tid = threadIdx.x;
    int lrow = tid & 127;
    int half = tid >> 7;
    int grow = (int)rank * 128 + lrow;

    ulonglong2 w[32];
    {
        const ulonglong2* wp =
            (const ulonglong2*)(i2h_W + (size_t)grow * 512 + 256 + half * 128);
        #pragma unroll
        for (int i = 0; i < 32; i++) w[i] = wp[i];
    }

    hs[0][tid] = h0[b * EMB + tid];
    const float* xp = xproj + (size_t)b * SEQ * EMB + grow;
    __syncthreads();

    int p = 0;
    for (int t = 0; t < SEQ; t++) {
        float xv = 0.f;
        if (half == 0) xv = xp[t * EMB];

        const ulonglong2* h2 = (const ulonglong2*)(hs[p] + half * 128);
        unsigned long long a0, a1, a2, a3;
        asm("mov.b64 %0, {%1, %2};" : "=l"(a0) : "f"(0.0f), "f"(0.0f));
        a1 = a0; a2 = a0; a3 = a0;
        #pragma unroll
        for (int i = 0; i < 32; i += 2) {
            ulonglong2 hv  = h2[i];
            ulonglong2 hv2 = h2[i + 1];
            FMA2(a0, w[i].x,     hv.x,  a0);
            FMA2(a1, w[i].y,     hv.y,  a1);
            FMA2(a2, w[i + 1].x, hv2.x, a2);
            FMA2(a3, w[i + 1].y, hv2.y, a3);
        }
        float f0, f1, f2, f3, f4, f5, f6, f7;
        asm("mov.b64 {%0, %1}, %2;" : "=f"(f0), "=f"(f1) : "l"(a0));
        asm("mov.b64 {%0, %1}, %2;" : "=f"(f2), "=f"(f3) : "l"(a1));
        asm("mov.b64 {%0, %1}, %2;" : "=f"(f4), "=f"(f5) : "l"(a2));
        asm("mov.b64 {%0, %1}, %2;" : "=f"(f6), "=f"(f7) : "l"(a3));
        part[tid] = ((f0 + f1) + (f2 + f3)) + ((f4 + f5) + (f6 + f7));
        __syncthreads();

        int pn = p ^ 1;
        if (half == 0) {
            float v = tanhf(xv + part[lrow] + part[128 + lrow]);
            v = v > 0.f ? v : 0.f;
            hs[pn][grow] = v;
            uint32_t la = smem_u32(&hs[pn][grow]);
            uint32_t ra;
            asm("mapa.shared::cluster.u32 %0, %1, %2;"
                : "=r"(ra) : "r"(la), "r"(rank ^ 1u));
            asm volatile("st.shared::cluster.f32 [%0], %1;"
                         :: "r"(ra), "f"(v) : "memory");
        }
        p = pn;
        asm volatile("barrier.cluster.arrive.aligned;" ::: "memory");
        asm volatile("barrier.cluster.wait.aligned;" ::: "memory");
    }
    if (half == 0) hlast[b * EMB + grow] = hs[p][grow];
}

// ============================================================================
// Final head
// ============================================================================
__global__ __launch_bounds__(256)
void final_kernel(const float* __restrict__ hlast, const float* __restrict__ h2o_W,
                  const float* __restrict__ h2o_b, const float* __restrict__ cls_W,
                  const float* __restrict__ cls_b, float* __restrict__ out)
{
    __shared__ float hs[EMB];
    __shared__ float red[EMB];
    int b = blockIdx.x, e = threadIdx.x;
    hs[e] = hlast[b * EMB + e];
    __syncthreads();

    float acc = h2o_b[e];
    const float4* wr = (const float4*)(h2o_W + (size_t)e * EMB);
    const float4* h4 = (const float4*)hs;
    #pragma unroll 16
    for (int k = 0; k < 64; k++) {
        float4 w = __ldg(&wr[k]);
        float4 hv = h4[k];
        acc += w.x*hv.x + w.y*hv.y + w.z*hv.z + w.w*hv.w;
    }
    out[OFF_SSM + b * EMB + e] = acc;
    red[e] = acc * cls_W[e];
    __syncthreads();
    #pragma unroll
    for (int o = 128; o; o >>= 1) {
        if (e < o) red[e] += red[e + o];
        __syncthreads();
    }
    if (e == 0) {
        float logit = red[0] + cls_b[0];
        out[b] = logit;
        out[OFF_PROBAS + b] = 1.f / (1.f + expf(-logit));
    }
}

// ============================================================================
extern "C" void kernel_launch(void* const* d_in, const int* in_sizes, int n_in,
                              void* d_out, int out_size)
{
    const float* text_emb = (const float*)d_in[0];
    const float* pos     = (const float*)d_in[4];
    const float* text_W  = (const float*)d_in[5];
    const float* text_b  = (const float*)d_in[6];
    const float* ln1_g   = (const float*)d_in[9];
    const float* ln1_b   = (const float*)d_in[10];
    const float* qkv_W   = (const float*)d_in[11];
    const float* qkv_b   = (const float*)d_in[12];
    const float* out_W   = (const float*)d_in[13];
    const float* out_b   = (const float*)d_in[14];
    const float* ln2_g   = (const float*)d_in[15];
    const float* ln2_b   = (const float*)d_in[16];
    const float* ffn_W1  = (const float*)d_in[17];
    const float* ffn_b1  = (const float*)d_in[18];
    const float* ffn_W2  = (const float*)d_in[19];
    const float* ffn_b2  = (const float*)d_in[20];
    const float* cls_W   = (const float*)d_in[21];
    const float* cls_b   = (const float*)d_in[22];
    const float* i2h_W   = (const float*)d_in[23];
    const float* i2h_b   = (const float*)d_in[24];
    const float* h2o_W   = (const float*)d_in[25];
    const float* h2o_b   = (const float*)d_in[26];
    const float* h0      = (const float*)d_in[27];
    float* out = (float*)d_out;

    float *x, *ln, *qkv, *ctx, *ffn, *xproj, *hlast;
    cudaGetSymbolAddress((void**)&x,     g_x);
    cudaGetSymbolAddress((void**)&ln,    g_ln);
    cudaGetSymbolAddress((void**)&qkv,   g_qkv);
    cudaGetSymbolAddress((void**)&ctx,   g_ctx);
    cudaGetSymbolAddress((void**)&ffn,   g_ffn);
    cudaGetSymbolAddress((void**)&xproj, g_xproj);
    cudaGetSymbolAddress((void**)&hlast, g_hlast);

    const int SMEM_GEMM = 2 * STAGE_BYTES;   // 73728 B
    cudaFuncSetAttribute(gemm_tc, cudaFuncAttributeMaxDynamicSharedMemorySize, SMEM_GEMM);

    // 1) lang = text_emb @ text_W^T + text_b + pos_emb
    gemm_tc<<<dim3(2, 128), 256, SMEM_GEMM>>>(text_emb, text_W, 768, text_b, nullptr, pos,
                                              x, nullptr, NTOK, EMB, 768, 0);

    // 2) two encoder layers (pre-LN)
    for (int l = 0; l < 2; l++) {
        ln_kernel<<<NTOK / 8, 256>>>(x, ln1_g + l * EMB, ln1_b + l * EMB, ln);
        gemm_tc<<<dim3(6, 128), 256, SMEM_GEMM>>>(ln, qkv_W + (size_t)l * 768 * EMB, EMB,
                                                  qkv_b + l * 768, nullptr, nullptr,
                                                  qkv, nullptr, NTOK, 768, EMB, 0);
        attn_tc<<<dim3(SEQ / 256, NHEAD, BATCH), 256>>>(qkv, ctx);
        gemm_tc<<<dim3(2, 128), 256, SMEM_GEMM>>>(ctx, out_W + (size_t)l * EMB * EMB, EMB,
                                                  out_b + l * EMB, x, nullptr,
                                                  x, nullptr, NTOK, EMB, EMB, 0);
        ln_kernel<<<NTOK / 8, 256>>>(x, ln2_g + l * EMB, ln2_b + l * EMB, ln);
        gemm_tc<<<dim3(8, 128), 256, SMEM_GEMM>>>(ln, ffn_W1 + (size_t)l * 1024 * EMB, EMB,
                                                  ffn_b1 + l * 1024, nullptr, nullptr,
                                                  ffn, nullptr, NTOK, 1024, EMB, 1);
        // layer 1's ffn2 also writes final_vector directly (copy fusion)
        gemm_tc<<<dim3(2, 128), 256, SMEM_GEMM>>>(ffn, ffn_W2 + (size_t)l * EMB * 1024, 1024,
                                                  ffn_b2 + l * EMB, x, nullptr,
                                                  x, (l == 1) ? (out + OFF_FINAL) : nullptr,
                                                  NTOK, EMB, 1024, 0);
    }

    // 3) xproj = x @ i2h_W[:, :256]^T + i2h_b  (row stride 512)
    gemm_tc<<<dim3(2, 128), 256, SMEM_GEMM>>>(x, i2h_W, 512, i2h_b, nullptr, nullptr,
                                              xproj, nullptr, NTOK, EMB, EMB, 0);

    // 4) sequential scan (cluster of 2 CTAs per batch, weights in registers)
    scan_kernel<<<BATCH * 2, 256>>>(xproj, i2h_W, h0, hlast);

    // 5) head
    final_kernel<<<BATCH, 256>>>(hlast, h2o_W, h2o_b, cls_W, cls_b, out);
}